// round 1
// baseline (speedup 1.0000x reference)
#include <cuda_runtime.h>
#include <cstdint>

#define KTAPS 7        // K+1 grid points per bin
#define NMAX  37       // max grid-point span per axis (34 px roi + slack)
#define PSTR  37       // patch row stride (odd -> conflict-free LDS)
#define RSTR  9        // rowdot row stride (odd -> conflict-free)
#define CH    64
#define HH    200
#define WW    304
#define SCALEF 0.0625f
#define NWARPS 8

#define PATCH_FLOATS (NMAX * PSTR)                 // 1369
#define RDOT_FLOATS  (NMAX * RSTR)                 // 333
#define PERWARP      (PATCH_FLOATS + RDOT_FLOATS)  // 1702
#define COMMON_OFF   (NWARPS * PERWARP)            // 13616 floats (8B aligned offset)
// common: cx[49] (8B each), cy[49] (8B each), misc[8]
#define SMEM_FLOATS  (COMMON_OFF + 49 * 2 * 2 + 16)
#define SMEM_BYTES   (SMEM_FLOATS * 4)

struct __align__(8) WI {
    float w;
    int   off;
};

__device__ __forceinline__ void cp_async4(void* dst, const void* src) {
    unsigned s = (unsigned)__cvta_generic_to_shared(dst);
    asm volatile("cp.async.ca.shared.global [%0], [%1], 4;" :: "r"(s), "l"(src));
}

__global__ __launch_bounds__(256) void prroi_kernel(
    const float* __restrict__ feats,
    const float* __restrict__ rois,
    float* __restrict__ out)
{
    extern __shared__ float sh[];
    WI*    sh_cx   = (WI*)(sh + COMMON_OFF);   // x-axis (weight, offset)
    WI*    sh_cy   = sh_cx + 49;               // y-axis (weight, offset)
    float* sh_misc = (float*)(sh_cy + 49);
    int*   sh_im   = (int*)sh_misc;
    // misc[0]=coef(f) [1]=b [2]=ylo [3]=xlo [4]=NR [5]=NX [6]=binszx(f) [7]=binszy(f)

    const int n   = blockIdx.x;
    const int tid = threadIdx.x;

    // ---- Phase 0: exact separable weights (replicates _axis_weights) ----
    if (tid < 14) {
        const int axis = (tid >= 7) ? 1 : 0;   // 0=x, 1=y
        const int p    = tid - axis * 7;
        const float lo = rois[n * 5 + 1 + axis] * SCALEF;
        const float hi = rois[n * 5 + 3 + axis] * SCALEF;
        const int size = axis ? HH : WW;
        const float length = fmaxf(hi - lo, 0.f);
        const float binsz  = length / 7.f;
        const float ws = lo + binsz * (float)p;
        const float we = ws + binsz;
        const float s  = floorf(ws);
        float Lk[6], Rk[6];
        #pragma unroll
        for (int k = 0; k < 6; k++) {
            const float cell = s + (float)k;
            const bool  act  = cell < we;
            const float x0 = fmaxf(ws, cell);
            const float x1 = fminf(we, cell + 1.f);
            const float a  = x0 - cell, la = x1 - cell;
            Lk[k] = act ? (la - 0.5f * la * la - a + 0.5f * a * a) : 0.f;
            const float a2 = cell + 1.f - x1, la2 = cell + 1.f - x0;
            Rk[k] = act ? (la2 - 0.5f * la2 * la2 - a2 + 0.5f * a2 * a2) : 0.f;
        }
        WI* dst = axis ? sh_cy : sh_cx;
        const int si = (int)s;
        #pragma unroll
        for (int t = 0; t < 7; t++) {
            float w = 0.f;
            if (t < 6) w += Lk[t];
            if (t > 0) w += Rk[t - 1];
            int idx = si + t;
            const bool valid = (idx >= 0) && (idx < size);
            w   = valid ? w : 0.f;
            idx = min(max(idx, 0), size - 1);
            dst[p * 7 + t].w   = w;
            dst[p * 7 + t].off = idx;   // absolute for now
        }
        if (p == 0) sh_misc[6 + axis] = binsz;
        if (tid == 0) sh_im[1] = (int)rois[n * 5];
    }
    __syncthreads();

    if (tid == 0) {
        const int xlo = sh_cx[0].off, xhi = sh_cx[48].off;
        const int ylo = sh_cy[0].off, yhi = sh_cy[48].off;
        sh_im[2] = ylo;
        sh_im[3] = xlo;
        sh_im[4] = yhi - ylo + 1;
        sh_im[5] = xhi - xlo + 1;
        const float win = sh_misc[6] * sh_misc[7];
        sh_misc[0] = (win > 0.f) ? (1.f / fmaxf(win, 1e-12f)) : 0.f;
    }
    __syncthreads();

    // convert absolute grid indices -> relative offsets
    if (tid < 49) {
        sh_cx[tid].off = sh_cx[tid].off - sh_im[3];
    } else if (tid >= 64 && tid < 113) {
        const int t = tid - 64;
        sh_cy[t].off = (sh_cy[t].off - sh_im[2]) * RSTR;
    }
    __syncthreads();

    const float coef = sh_misc[0];
    const int b   = sh_im[1];
    const int ylo = sh_im[2], xlo = sh_im[3];
    const int NR  = sh_im[4], NX  = sh_im[5];

    const int warp = tid >> 5, lane = tid & 31;
    float* patch = sh + warp * PERWARP;
    float* rdot  = patch + PATCH_FLOATS;

    const float* fbase = feats + ((size_t)b * CH) * (HH * WW)
                               + (size_t)ylo * WW + xlo;

    for (int c = warp; c < CH; c += NWARPS) {
        const float* src = fbase + (size_t)c * (HH * WW);

        // ---- stage patch into shared (coalesced, high-MLP via cp.async) ----
        for (int r = 0; r < NR; r++) {
            const float* srow = src + r * WW;
            float* drow = patch + r * PSTR;
            for (int x = lane; x < NX; x += 32)
                cp_async4(drow + x, srow + x);
        }
        asm volatile("cp.async.commit_group;");
        asm volatile("cp.async.wait_group 0;");
        __syncwarp();

        // ---- stage 1: rowdot[r][j] = sum_b Wx[j,b] * patch[r, gxrel[j,b]] ----
        for (int r = lane; r < NR; r += 32) {
            const float* prow = patch + r * PSTR;
            float* rrow = rdot + r * RSTR;
            #pragma unroll
            for (int j = 0; j < 7; j++) {
                float acc = 0.f;
                #pragma unroll
                for (int bb = 0; bb < 7; bb++) {
                    const WI e = sh_cx[j * 7 + bb];
                    acc = fmaf(e.w, prow[e.off], acc);
                }
                rrow[j] = acc;
            }
        }
        __syncwarp();

        // ---- stage 2: out[i][j] = coef * sum_a Wy[i,a] * rowdot[gyrel[i,a]][j] ----
        float* outc = out + ((size_t)n * CH + c) * 49;
        #pragma unroll
        for (int half = 0; half < 2; half++) {
            const int it = lane + half * 32;
            if (it < 49) {
                const int i = it / 7;
                const int j = it - i * 7;
                float acc = 0.f;
                #pragma unroll
                for (int a = 0; a < 7; a++) {
                    const WI e = sh_cy[i * 7 + a];
                    acc = fmaf(e.w, rdot[e.off + j], acc);
                }
                outc[it] = acc * coef;
            }
        }
        __syncwarp();
    }
}

extern "C" void kernel_launch(void* const* d_in, const int* in_sizes, int n_in,
                              void* d_out, int out_size) {
    const float* feats = (const float*)d_in[0];
    const float* rois  = (const float*)d_in[1];
    float* out = (float*)d_out;
    const int N = in_sizes[1] / 5;

    cudaFuncSetAttribute(prroi_kernel,
                         cudaFuncAttributeMaxDynamicSharedMemorySize, SMEM_BYTES);
    prroi_kernel<<<N, 256, SMEM_BYTES>>>(feats, rois, out);
}

// round 4
// speedup vs baseline: 1.3065x; 1.3065x over previous
#include <cuda_runtime.h>
#include <cstdint>

#define NMAX  37       // max grid-point span per axis
#define CH    64
#define HH    200
#define WW    304
#define HW    (HH * WW)
#define SCALEF 0.0625f
#define NWARPS 8

struct __align__(8) WI {
    float w;
    int   off;
};

__global__ __launch_bounds__(256) void prroi_kernel(
    const float* __restrict__ feats,
    const float* __restrict__ rois,
    float* __restrict__ out)
{
    __shared__ __align__(16) float s_wyd[NMAX * 8];   // dense y weights: [r][i], stride 8
    __shared__ WI    s_cy[49];                         // y taps: UNCLIPPED abs idx + weight
    __shared__ WI    s_cxr[49];                        // x taps: converted (w, xrel*7)
    __shared__ WI    s_cx[49];                         // x taps: UNCLIPPED abs idx + weight
    __shared__ float s_misc[8];                        // [6]=binszx [7]=binszy
    __shared__ __align__(16) float s_cold[NWARPS][2][260]; // per-warp coldot, 2 channels

    const int n   = blockIdx.x;
    const int tid = threadIdx.x;

    // zero dense y-weight table (all threads)
    for (int k = tid; k < NMAX * 8; k += 256) s_wyd[k] = 0.f;

    // ---- Phase 0: exact separable 1-D weights (replicates _axis_weights) ----
    if (tid < 14) {
        const int axis = (tid >= 7) ? 1 : 0;   // 0=x, 1=y
        const int p    = tid - axis * 7;
        const float lo = __ldg(&rois[n * 5 + 1 + axis]) * SCALEF;
        const float hi = __ldg(&rois[n * 5 + 3 + axis]) * SCALEF;
        const int size = axis ? HH : WW;
        const float length = fmaxf(hi - lo, 0.f);
        const float binsz  = length / 7.f;
        const float ws = lo + binsz * (float)p;
        const float we = ws + binsz;
        const float s  = floorf(ws);
        float Lk[6], Rk[6];
        #pragma unroll
        for (int k = 0; k < 6; k++) {
            const float cell = s + (float)k;
            const bool  act  = cell < we;
            const float x0 = fmaxf(ws, cell);
            const float x1 = fminf(we, cell + 1.f);
            const float a  = x0 - cell, la = x1 - cell;
            Lk[k] = act ? (la - 0.5f * la * la - a + 0.5f * a * a) : 0.f;
            const float a2 = cell + 1.f - x1, la2 = cell + 1.f - x0;
            Rk[k] = act ? (la2 - 0.5f * la2 * la2 - a2 + 0.5f * a2 * a2) : 0.f;
        }
        WI* dst = axis ? s_cy : s_cx;
        const int si = (int)s;
        #pragma unroll
        for (int t = 0; t < 7; t++) {
            float w = 0.f;
            if (t < 6) w += Lk[t];
            if (t > 0) w += Rk[t - 1];
            const int idx = si + t;                 // UNCLIPPED
            const bool valid = (idx >= 0) && (idx < size);
            dst[p * 7 + t].w   = valid ? w : 0.f;
            dst[p * 7 + t].off = idx;
        }
        if (p == 0) s_misc[6 + axis] = binsz;
    }
    __syncthreads();

    // ---- every thread derives bounds locally (read-only on taps) ----
    const int b = (int)__ldg(&rois[n * 5]);
    const int xlo = min(max(s_cx[0].off,  0), WW - 1);
    const int xhi = min(max(s_cx[48].off, 0), WW - 1);
    const int ylo = min(max(s_cy[0].off,  0), HH - 1);
    const int yhi = min(max(s_cy[48].off, 0), HH - 1);
    const int NX = xhi - xlo + 1;
    const int NR = yhi - ylo + 1;
    const float win = s_misc[6] * s_misc[7];
    const float coef = (win > 0.f) ? (1.f / fmaxf(win, 1e-12f)) : 0.f;

    // ---- convert x taps + scatter dense y weights (unique slots, no races) ----
    if (tid < 49) {
        const WI ex = s_cx[tid];
        WI o;
        o.w = ex.w;
        o.off = (min(max(ex.off, 0), WW - 1) - xlo) * 7;
        s_cxr[tid] = o;

        const WI ey = s_cy[tid];
        if (ey.off >= 0 && ey.off < HH) {
            // (i, row) unique across valid taps -> race-free add
            s_wyd[(ey.off - ylo) * 8 + tid / 7] += ey.w;
        }
    }
    __syncthreads();

    const int warp = tid >> 5, lane = tid & 31;
    float* sc0 = s_cold[warp][0];
    float* sc1 = s_cold[warp][1];

    const float* base = feats + ((size_t)b * CH) * HW + (size_t)ylo * WW + xlo;

    // channels: warp handles (warp + 16k) and (warp + 8 + 16k), k = 0..3
    #pragma unroll 1
    for (int k = 0; k < 4; k++) {
        const int c0 = warp + k * 16;
        const float* p0 = base + (size_t)c0 * HW;
        const float* p1 = p0 + (size_t)NWARPS * HW;

        // ---- column-dot: cd[i] = sum_r WyD[r][i] * F[r, x] ----
        for (int xb = 0; xb < NX; xb += 32) {
            const int x = xb + lane;
            const bool act = x < NX;
            float ca[7], cb[7];
            #pragma unroll
            for (int i = 0; i < 7; i++) { ca[i] = 0.f; cb[i] = 0.f; }

            const float* q0 = p0 + x;
            const float* q1 = p1 + x;
            #pragma unroll 2
            for (int r = 0; r < NR; r++) {
                const float v0 = act ? __ldg(q0 + r * WW) : 0.f;
                const float v1 = act ? __ldg(q1 + r * WW) : 0.f;
                const float4 wA = *(const float4*)(s_wyd + r * 8);
                const float4 wB = *(const float4*)(s_wyd + r * 8 + 4);
                ca[0] = fmaf(wA.x, v0, ca[0]);  cb[0] = fmaf(wA.x, v1, cb[0]);
                ca[1] = fmaf(wA.y, v0, ca[1]);  cb[1] = fmaf(wA.y, v1, cb[1]);
                ca[2] = fmaf(wA.z, v0, ca[2]);  cb[2] = fmaf(wA.z, v1, cb[2]);
                ca[3] = fmaf(wA.w, v0, ca[3]);  cb[3] = fmaf(wA.w, v1, cb[3]);
                ca[4] = fmaf(wB.x, v0, ca[4]);  cb[4] = fmaf(wB.x, v1, cb[4]);
                ca[5] = fmaf(wB.y, v0, ca[5]);  cb[5] = fmaf(wB.y, v1, cb[5]);
                ca[6] = fmaf(wB.z, v0, ca[6]);  cb[6] = fmaf(wB.z, v1, cb[6]);
            }
            if (act) {
                #pragma unroll
                for (int i = 0; i < 7; i++) {
                    sc0[x * 7 + i] = ca[i];
                    sc1[x * 7 + i] = cb[i];
                }
            }
        }
        __syncwarp();

        // ---- x-combine: out[i][j] = coef * sum_b Wx[j,b] * coldot[gxrel][i] ----
        float* o0 = out + ((size_t)n * CH + c0) * 49;
        float* o1 = o0 + (size_t)NWARPS * 49;
        #pragma unroll
        for (int half = 0; half < 2; half++) {
            const int it = lane + half * 32;
            if (it < 49) {
                const int i = it / 7;
                const int j = it - i * 7;
                float a0 = 0.f, a1 = 0.f;
                #pragma unroll
                for (int bb = 0; bb < 7; bb++) {
                    const WI e = s_cxr[j * 7 + bb];
                    a0 = fmaf(e.w, sc0[e.off + i], a0);
                    a1 = fmaf(e.w, sc1[e.off + i], a1);
                }
                o0[it] = a0 * coef;
                o1[it] = a1 * coef;
            }
        }
        __syncwarp();
    }
}

extern "C" void kernel_launch(void* const* d_in, const int* in_sizes, int n_in,
                              void* d_out, int out_size) {
    const float* feats = (const float*)d_in[0];
    const float* rois  = (const float*)d_in[1];
    float* out = (float*)d_out;
    const int N = in_sizes[1] / 5;
    prroi_kernel<<<N, 256>>>(feats, rois, out);
}

// round 9
// speedup vs baseline: 2.3951x; 1.8332x over previous
#include <cuda_runtime.h>
#include <cstdint>

#define NMAX  37       // max grid-point span per axis
#define CH    64
#define HH    200
#define WW    304
#define HW    (HH * WW)
#define SCALEF 0.0625f
#define NWARPS 4       // warps per block
#define CGRP  8        // channel groups (blocks per roi); CH/CGRP = 8 ch/block

struct __align__(8) WI {
    float w;
    int   off;
};

__global__ __launch_bounds__(128) void prroi_kernel(
    const float* __restrict__ feats,
    const float* __restrict__ rois,
    float* __restrict__ out)
{
    __shared__ __align__(16) float s_wyd[NMAX * 8];   // dense y weights: [r][i], stride 8
    __shared__ WI    s_cy[49];                         // y taps: UNCLIPPED abs idx + weight
    __shared__ WI    s_cxr[49];                        // x taps: converted (w, xrel*7)
    __shared__ WI    s_cx[49];                         // x taps: UNCLIPPED abs idx + weight
    __shared__ float s_misc[8];                        // [6]=binszx [7]=binszy
    __shared__ __align__(16) float s_cold[NWARPS][2][260]; // per-warp coldot, 2 channels

    const int n   = blockIdx.x;
    const int g   = blockIdx.y;          // channel group
    const int tid = threadIdx.x;

    // zero dense y-weight table (all threads)
    for (int k = tid; k < NMAX * 8; k += 128) s_wyd[k] = 0.f;

    // ---- Phase 0: exact separable 1-D weights (replicates _axis_weights) ----
    if (tid < 14) {
        const int axis = (tid >= 7) ? 1 : 0;   // 0=x, 1=y
        const int p    = tid - axis * 7;
        const float lo = __ldg(&rois[n * 5 + 1 + axis]) * SCALEF;
        const float hi = __ldg(&rois[n * 5 + 3 + axis]) * SCALEF;
        const int size = axis ? HH : WW;
        const float length = fmaxf(hi - lo, 0.f);
        const float binsz  = length / 7.f;
        const float ws = lo + binsz * (float)p;
        const float we = ws + binsz;
        const float s  = floorf(ws);
        float Lk[6], Rk[6];
        #pragma unroll
        for (int k = 0; k < 6; k++) {
            const float cell = s + (float)k;
            const bool  act  = cell < we;
            const float x0 = fmaxf(ws, cell);
            const float x1 = fminf(we, cell + 1.f);
            const float a  = x0 - cell, la = x1 - cell;
            Lk[k] = act ? (la - 0.5f * la * la - a + 0.5f * a * a) : 0.f;
            const float a2 = cell + 1.f - x1, la2 = cell + 1.f - x0;
            Rk[k] = act ? (la2 - 0.5f * la2 * la2 - a2 + 0.5f * a2 * a2) : 0.f;
        }
        WI* dst = axis ? s_cy : s_cx;
        const int si = (int)s;
        #pragma unroll
        for (int t = 0; t < 7; t++) {
            float w = 0.f;
            if (t < 6) w += Lk[t];
            if (t > 0) w += Rk[t - 1];
            const int idx = si + t;                 // UNCLIPPED
            const bool valid = (idx >= 0) && (idx < size);
            dst[p * 7 + t].w   = valid ? w : 0.f;
            dst[p * 7 + t].off = idx;
        }
        if (p == 0) s_misc[6 + axis] = binsz;
    }
    __syncthreads();

    // ---- every thread derives bounds locally (read-only on taps) ----
    const int b = (int)__ldg(&rois[n * 5]);
    const int xlo = min(max(s_cx[0].off,  0), WW - 1);
    const int xhi = min(max(s_cx[48].off, 0), WW - 1);
    const int ylo = min(max(s_cy[0].off,  0), HH - 1);
    const int yhi = min(max(s_cy[48].off, 0), HH - 1);
    const int NX = xhi - xlo + 1;
    const int NR = yhi - ylo + 1;
    const float win = s_misc[6] * s_misc[7];
    const float coef = (win > 0.f) ? (1.f / fmaxf(win, 1e-12f)) : 0.f;

    // ---- convert x taps + scatter dense y weights (unique slots, no races) ----
    if (tid < 49) {
        const WI ex = s_cx[tid];
        WI o;
        o.w = ex.w;
        o.off = (min(max(ex.off, 0), WW - 1) - xlo) * 7;
        s_cxr[tid] = o;

        const WI ey = s_cy[tid];
        if (ey.off >= 0 && ey.off < HH) {
            // (i, row) unique across valid taps -> race-free add
            s_wyd[(ey.off - ylo) * 8 + tid / 7] += ey.w;
        }
    }
    __syncthreads();

    const int warp = tid >> 5, lane = tid & 31;
    float* sc0 = s_cold[warp][0];
    float* sc1 = s_cold[warp][1];

    const float* base = feats + ((size_t)b * CH) * HW + (size_t)ylo * WW + xlo;

    // this block handles channels [g*8, g*8+8); warp handles c0 and c0+4
    const int c0 = g * (CH / CGRP) + warp;
    const float* p0 = base + (size_t)c0 * HW;
    const float* p1 = p0 + (size_t)NWARPS * HW;

    // ---- column-dot: cd[i] = sum_r WyD[r][i] * F[r, x] ----
    for (int xb = 0; xb < NX; xb += 32) {
        const int x = xb + lane;
        const bool act = x < NX;
        float ca[7], cb[7];
        #pragma unroll
        for (int i = 0; i < 7; i++) { ca[i] = 0.f; cb[i] = 0.f; }

        const float* q0 = p0 + x;
        const float* q1 = p1 + x;
        #pragma unroll 2
        for (int r = 0; r < NR; r++) {
            const float v0 = act ? __ldg(q0 + r * WW) : 0.f;
            const float v1 = act ? __ldg(q1 + r * WW) : 0.f;
            const float4 wA = *(const float4*)(s_wyd + r * 8);
            const float4 wB = *(const float4*)(s_wyd + r * 8 + 4);
            ca[0] = fmaf(wA.x, v0, ca[0]);  cb[0] = fmaf(wA.x, v1, cb[0]);
            ca[1] = fmaf(wA.y, v0, ca[1]);  cb[1] = fmaf(wA.y, v1, cb[1]);
            ca[2] = fmaf(wA.z, v0, ca[2]);  cb[2] = fmaf(wA.z, v1, cb[2]);
            ca[3] = fmaf(wA.w, v0, ca[3]);  cb[3] = fmaf(wA.w, v1, cb[3]);
            ca[4] = fmaf(wB.x, v0, ca[4]);  cb[4] = fmaf(wB.x, v1, cb[4]);
            ca[5] = fmaf(wB.y, v0, ca[5]);  cb[5] = fmaf(wB.y, v1, cb[5]);
            ca[6] = fmaf(wB.z, v0, ca[6]);  cb[6] = fmaf(wB.z, v1, cb[6]);
        }
        if (act) {
            #pragma unroll
            for (int i = 0; i < 7; i++) {
                sc0[x * 7 + i] = ca[i];
                sc1[x * 7 + i] = cb[i];
            }
        }
    }
    __syncwarp();

    // ---- x-combine: out[i][j] = coef * sum_b Wx[j,b] * coldot[gxrel][i] ----
    float* o0 = out + ((size_t)n * CH + c0) * 49;
    float* o1 = o0 + (size_t)NWARPS * 49;
    #pragma unroll
    for (int half = 0; half < 2; half++) {
        const int it = lane + half * 32;
        if (it < 49) {
            const int i = it / 7;
            const int j = it - i * 7;
            float a0 = 0.f, a1 = 0.f;
            #pragma unroll
            for (int bb = 0; bb < 7; bb++) {
                const WI e = s_cxr[j * 7 + bb];
                a0 = fmaf(e.w, sc0[e.off + i], a0);
                a1 = fmaf(e.w, sc1[e.off + i], a1);
            }
            o0[it] = a0 * coef;
            o1[it] = a1 * coef;
        }
    }
}

extern "C" void kernel_launch(void* const* d_in, const int* in_sizes, int n_in,
                              void* d_out, int out_size) {
    const float* feats = (const float*)d_in[0];
    const float* rois  = (const float*)d_in[1];
    float* out = (float*)d_out;
    const int N = in_sizes[1] / 5;
    prroi_kernel<<<dim3(N, CGRP), 128>>>(feats, rois, out);
}

// round 10
// speedup vs baseline: 2.9436x; 1.2290x over previous
#include <cuda_runtime.h>
#include <cstdint>

#define NMAX  37       // max grid-point span per axis
#define CH    64
#define HH    200
#define WW    304
#define HW    (HH * WW)
#define SCALEF 0.0625f
#define NWARPS 4       // warps per block
#define CGRP  8        // channel groups (blocks per roi); CH/CGRP = 8 ch/block

struct __align__(8) WI {
    float w;
    int   off;
};

__global__ __launch_bounds__(128) void prroi_kernel(
    const float* __restrict__ feats,
    const float* __restrict__ rois,
    float* __restrict__ out)
{
    __shared__ __align__(16) float s_wyd[NMAX * 8];   // dense y weights: [r][i], stride 8
    __shared__ WI    s_cy[49];                         // y taps: UNCLIPPED abs idx + weight
    __shared__ WI    s_cxr[49];                        // x taps: converted (w, xrel*7)
    __shared__ WI    s_cx[49];                         // x taps: UNCLIPPED abs idx + weight
    __shared__ float s_misc[8];                        // [6]=binszx [7]=binszy
    __shared__ __align__(16) float s_cold[NWARPS][2][260]; // per-warp coldot, 2 channels

    const int n   = blockIdx.x;
    const int g   = blockIdx.y;          // channel group
    const int tid = threadIdx.x;

    // zero dense y-weight table (all threads)
    for (int k = tid; k < NMAX * 8; k += 128) s_wyd[k] = 0.f;

    // ---- Phase 0: exact separable 1-D weights (replicates _axis_weights) ----
    if (tid < 14) {
        const int axis = (tid >= 7) ? 1 : 0;   // 0=x, 1=y
        const int p    = tid - axis * 7;
        const float lo = __ldg(&rois[n * 5 + 1 + axis]) * SCALEF;
        const float hi = __ldg(&rois[n * 5 + 3 + axis]) * SCALEF;
        const int size = axis ? HH : WW;
        const float length = fmaxf(hi - lo, 0.f);
        const float binsz  = length / 7.f;
        const float ws = lo + binsz * (float)p;
        const float we = ws + binsz;
        const float s  = floorf(ws);
        float Lk[6], Rk[6];
        #pragma unroll
        for (int k = 0; k < 6; k++) {
            const float cell = s + (float)k;
            const bool  act  = cell < we;
            const float x0 = fmaxf(ws, cell);
            const float x1 = fminf(we, cell + 1.f);
            const float a  = x0 - cell, la = x1 - cell;
            Lk[k] = act ? (la - 0.5f * la * la - a + 0.5f * a * a) : 0.f;
            const float a2 = cell + 1.f - x1, la2 = cell + 1.f - x0;
            Rk[k] = act ? (la2 - 0.5f * la2 * la2 - a2 + 0.5f * a2 * a2) : 0.f;
        }
        WI* dst = axis ? s_cy : s_cx;
        const int si = (int)s;
        #pragma unroll
        for (int t = 0; t < 7; t++) {
            float w = 0.f;
            if (t < 6) w += Lk[t];
            if (t > 0) w += Rk[t - 1];
            const int idx = si + t;                 // UNCLIPPED
            const bool valid = (idx >= 0) && (idx < size);
            dst[p * 7 + t].w   = valid ? w : 0.f;
            dst[p * 7 + t].off = idx;
        }
        if (p == 0) s_misc[6 + axis] = binsz;
    }
    __syncthreads();

    // ---- every thread derives bounds locally (read-only on taps) ----
    const int b = (int)__ldg(&rois[n * 5]);
    const int xlo = min(max(s_cx[0].off,  0), WW - 1);
    const int xhi = min(max(s_cx[48].off, 0), WW - 1);
    const int ylo = min(max(s_cy[0].off,  0), HH - 1);
    const int yhi = min(max(s_cy[48].off, 0), HH - 1);
    const int NX = xhi - xlo + 1;
    const int NR = yhi - ylo + 1;
    const float win = s_misc[6] * s_misc[7];
    const float coef = (win > 0.f) ? (1.f / fmaxf(win, 1e-12f)) : 0.f;

    // ---- convert x taps + scatter dense y weights (unique slots, no races) ----
    if (tid < 49) {
        const WI ex = s_cx[tid];
        WI o;
        o.w = ex.w;
        o.off = (min(max(ex.off, 0), WW - 1) - xlo) * 7;
        s_cxr[tid] = o;

        const WI ey = s_cy[tid];
        if (ey.off >= 0 && ey.off < HH) {
            // (i, row) unique across valid taps -> race-free add
            s_wyd[(ey.off - ylo) * 8 + tid / 7] += ey.w;
        }
    }
    __syncthreads();

    const int warp = tid >> 5, lane = tid & 31;
    float* sc0 = s_cold[warp][0];
    float* sc1 = s_cold[warp][1];

    const float* base = feats + ((size_t)b * CH) * HW + (size_t)ylo * WW + xlo;

    // this block handles channels [g*8, g*8+8); warp handles c0 and c0+4
    const int c0 = g * (CH / CGRP) + warp;
    const float* p0 = base + (size_t)c0 * HW;
    const float* p1 = p0 + (size_t)NWARPS * HW;

    // ---- column-dot: cd[i] = sum_r WyD[r][i] * F[r, x] ----
    for (int xb = 0; xb < NX; xb += 32) {
        const int x = xb + lane;
        const bool act = x < NX;
        float ca[7], cb[7];
        #pragma unroll
        for (int i = 0; i < 7; i++) { ca[i] = 0.f; cb[i] = 0.f; }

        const float* q0 = p0 + x;
        const float* q1 = p1 + x;

        int r = 0;
        // main: 4 rows per chunk, loads explicitly front-batched (MLP = 8)
        for (; r + 3 < NR; r += 4) {
            float v0[4], v1[4];
            #pragma unroll
            for (int u = 0; u < 4; u++) {
                v0[u] = act ? __ldg(q0 + (r + u) * WW) : 0.f;
                v1[u] = act ? __ldg(q1 + (r + u) * WW) : 0.f;
            }
            #pragma unroll
            for (int u = 0; u < 4; u++) {
                const float4 wA = *(const float4*)(s_wyd + (r + u) * 8);
                const float4 wB = *(const float4*)(s_wyd + (r + u) * 8 + 4);
                ca[0] = fmaf(wA.x, v0[u], ca[0]);  cb[0] = fmaf(wA.x, v1[u], cb[0]);
                ca[1] = fmaf(wA.y, v0[u], ca[1]);  cb[1] = fmaf(wA.y, v1[u], cb[1]);
                ca[2] = fmaf(wA.z, v0[u], ca[2]);  cb[2] = fmaf(wA.z, v1[u], cb[2]);
                ca[3] = fmaf(wA.w, v0[u], ca[3]);  cb[3] = fmaf(wA.w, v1[u], cb[3]);
                ca[4] = fmaf(wB.x, v0[u], ca[4]);  cb[4] = fmaf(wB.x, v1[u], cb[4]);
                ca[5] = fmaf(wB.y, v0[u], ca[5]);  cb[5] = fmaf(wB.y, v1[u], cb[5]);
                ca[6] = fmaf(wB.z, v0[u], ca[6]);  cb[6] = fmaf(wB.z, v1[u], cb[6]);
            }
        }
        // remainder rows
        for (; r < NR; r++) {
            const float v0 = act ? __ldg(q0 + r * WW) : 0.f;
            const float v1 = act ? __ldg(q1 + r * WW) : 0.f;
            const float4 wA = *(const float4*)(s_wyd + r * 8);
            const float4 wB = *(const float4*)(s_wyd + r * 8 + 4);
            ca[0] = fmaf(wA.x, v0, ca[0]);  cb[0] = fmaf(wA.x, v1, cb[0]);
            ca[1] = fmaf(wA.y, v0, ca[1]);  cb[1] = fmaf(wA.y, v1, cb[1]);
            ca[2] = fmaf(wA.z, v0, ca[2]);  cb[2] = fmaf(wA.z, v1, cb[2]);
            ca[3] = fmaf(wA.w, v0, ca[3]);  cb[3] = fmaf(wA.w, v1, cb[3]);
            ca[4] = fmaf(wB.x, v0, ca[4]);  cb[4] = fmaf(wB.x, v1, cb[4]);
            ca[5] = fmaf(wB.y, v0, ca[5]);  cb[5] = fmaf(wB.y, v1, cb[5]);
            ca[6] = fmaf(wB.z, v0, ca[6]);  cb[6] = fmaf(wB.z, v1, cb[6]);
        }

        if (act) {
            #pragma unroll
            for (int i = 0; i < 7; i++) {
                sc0[x * 7 + i] = ca[i];
                sc1[x * 7 + i] = cb[i];
            }
        }
    }
    __syncwarp();

    // ---- x-combine: out[i][j] = coef * sum_b Wx[j,b] * coldot[gxrel][i] ----
    float* o0 = out + ((size_t)n * CH + c0) * 49;
    float* o1 = o0 + (size_t)NWARPS * 49;
    #pragma unroll
    for (int half = 0; half < 2; half++) {
        const int it = lane + half * 32;
        if (it < 49) {
            const int i = it / 7;
            const int j = it - i * 7;
            float a0 = 0.f, a1 = 0.f;
            #pragma unroll
            for (int bb = 0; bb < 7; bb++) {
                const WI e = s_cxr[j * 7 + bb];
                a0 = fmaf(e.w, sc0[e.off + i], a0);
                a1 = fmaf(e.w, sc1[e.off + i], a1);
            }
            o0[it] = a0 * coef;
            o1[it] = a1 * coef;
        }
    }
}

extern "C" void kernel_launch(void* const* d_in, const int* in_sizes, int n_in,
                              void* d_out, int out_size) {
    const float* feats = (const float*)d_in[0];
    const float* rois  = (const float*)d_in[1];
    float* out = (float*)d_out;
    const int N = in_sizes[1] / 5;
    prroi_kernel<<<dim3(N, CGRP), 128>>>(feats, rois, out);
}